// round 17
// baseline (speedup 1.0000x reference)
#include <cuda_runtime.h>
#include <cuda_fp16.h>
#include <math.h>
#include <stdint.h>

#define B_    2
#define S_    2048
#define H_    16
#define D_    64
#define HID   1024
#define QKV_  1024
#define M_TOK 4096
#define N_QKV 3072
#define SCALE 0.125f

typedef unsigned long long u64;
typedef __half f16;

// ---------------- helpers ----------------------------------------------------
__device__ __forceinline__ uint32_t packh(float x, float y) {
    __half2 h = __floats2half2_rn(x, y);
    return *(uint32_t*)&h;
}
__device__ __forceinline__ void mmah(float* d,
    uint32_t a0, uint32_t a1, uint32_t a2, uint32_t a3, uint32_t b0, uint32_t b1) {
    asm volatile(
        "mma.sync.aligned.m16n8k16.row.col.f32.f16.f16.f32 "
        "{%0,%1,%2,%3},{%4,%5,%6,%7},{%8,%9},{%0,%1,%2,%3};"
        : "+f"(d[0]), "+f"(d[1]), "+f"(d[2]), "+f"(d[3])
        : "r"(a0), "r"(a1), "r"(a2), "r"(a3), "r"(b0), "r"(b1));
}
__device__ __forceinline__ void ldsm4(uint32_t* r, uint32_t addr) {
    asm volatile("ldmatrix.sync.aligned.m8n8.x4.shared.b16 {%0,%1,%2,%3},[%4];"
                 : "=r"(r[0]), "=r"(r[1]), "=r"(r[2]), "=r"(r[3]) : "r"(addr));
}
__device__ __forceinline__ void ldsm4t(uint32_t* r, uint32_t addr) {
    asm volatile("ldmatrix.sync.aligned.m8n8.x4.trans.shared.b16 {%0,%1,%2,%3},[%4];"
                 : "=r"(r[0]), "=r"(r[1]), "=r"(r[2]), "=r"(r[3]) : "r"(addr));
}
__device__ __forceinline__ uint32_t smem_u32(const void* p) {
    uint32_t a;
    asm("{ .reg .u64 t; cvta.to.shared.u64 t, %1; cvt.u32.u64 %0, t; }" : "=r"(a) : "l"(p));
    return a;
}
__device__ __forceinline__ void bulkcp(uint32_t dst, const void* src,
                                       uint32_t bytes, uint32_t mbar) {
    asm volatile(
        "cp.async.bulk.shared::cluster.global.mbarrier::complete_tx::bytes "
        "[%0], [%1], %2, [%3];"
        :: "r"(dst), "l"(src), "r"(bytes), "r"(mbar) : "memory");
}
#define MBAR_INIT(a, c) \
    asm volatile("mbarrier.init.shared.b64 [%0], %1;" :: "r"(a), "r"(c) : "memory")
#define MBAR_EXPECT(a, bytes) \
    asm volatile("mbarrier.arrive.expect_tx.shared.b64 _, [%0], %1;" \
                 :: "r"(a), "r"(bytes) : "memory")
#define MBAR_ARRIVE(a) \
    asm volatile("mbarrier.arrive.shared.b64 _, [%0];" :: "r"(a) : "memory")
#define MBAR_WAIT(a, ph) do {                                                  \
    uint32_t _m = (a); uint32_t _p = (ph); uint32_t _done;                     \
    asm volatile("{ .reg .pred p; mbarrier.try_wait.parity.acquire.cta.shared::cta.b64 p, [%1], %2;" \
                 " selp.b32 %0,1,0,p; }" : "=r"(_done) : "r"(_m), "r"(_p) : "memory"); \
    if (!_done) {                                                              \
        asm volatile("{ .reg .pred P1; WL_%=:"                                 \
                     " mbarrier.try_wait.parity.acquire.cta.shared::cta.b64 P1, [%0], %1, 0x989680;" \
                     " @P1 bra.uni WD_%=; bra.uni WL_%=; WD_%=: }"             \
                     :: "r"(_m), "r"(_p) : "memory");                          \
    }                                                                          \
} while (0)

// ---------------- tiled layout constants -------------------------------------
#define GLD2 40
#define APIECE (128 * GLD2)
#define AQLD 72
#define KPIECE (128 * AQLD)
#define KSUB (64 * AQLD)

// ---------------- scratch ----------------------------------------------------
__device__ f16 g_xh[(size_t)32 * 32 * APIECE];
__device__ f16 g_wqh[(size_t)24 * 32 * APIECE];
__device__ f16 g_woh[(size_t)8 * 32 * APIECE];
__device__ f16 g_ath[(size_t)32 * 32 * APIECE];
__device__ f16 g_qh[(size_t)512 * KPIECE];
__device__ f16 g_kh[(size_t)512 * KPIECE];
__device__ f16 g_vh[(size_t)512 * KPIECE];

// ---------------------------------------------------------------------------
// split pre-pass: fp32 row-major [R][C] -> tiled fp16
// ---------------------------------------------------------------------------
__global__ __launch_bounds__(256) void split_tiled(
    const float* __restrict__ src, f16* __restrict__ h, int C)
{
    const size_t e = ((size_t)blockIdx.x * 256 + threadIdx.x) * 8;
    const int r = (int)(e / C), c = (int)(e % C);
    float4 a = *(const float4*)(src + e);
    float4 b = *(const float4*)(src + e + 4);
    const size_t dst = ((size_t)((r >> 7) * (C >> 5) + (c >> 5))) * APIECE
                     + (size_t)(r & 127) * GLD2 + (c & 31);
    *(uint4*)(h + dst) = make_uint4(packh(a.x, a.y), packh(a.z, a.w),
                                    packh(b.x, b.y), packh(b.z, b.w));
}

// ---------------------------------------------------------------------------
// fp16 NT GEMM: CTA 128x64, 8 warps (32x32 warp tile), 4-stage pipeline,
// 3 CTAs/SM. kmode=1: emit Q(scaled)/K/V fp16 tiles. kmode=0: fp32 C + bias.
// ---------------------------------------------------------------------------
#define GAT_B (128 * GLD2 * 2)        // A piece bytes = 10240
#define GBT_B (64 * GLD2 * 2)         // B 64-row sub-piece = 5120
#define STG2 (GAT_B + GBT_B)          // 15360
#define GNST 4
#define GEMM_SMEM (GNST * STG2 + 64)  // 61504

__global__ __launch_bounds__(256, 3) void gemm_f16(
    const f16* __restrict__ Ah, const f16* __restrict__ Bh,
    const float* __restrict__ bias, float* __restrict__ C,
    f16* __restrict__ qh, f16* __restrict__ kh, f16* __restrict__ vh,
    int M, int N, int K, int kmode)
{
    extern __shared__ char smem[];
    const uint32_t sb = smem_u32(smem);
    const uint32_t dbar = sb + GNST * STG2;
    const uint32_t fbar = dbar + 32;

    const int tid = threadIdx.x;
    const int wid = tid >> 5;
    const int lid = tid & 31;
    const int g   = lid >> 2;
    const int tg  = lid & 3;
    const int wm  = (wid & 3) * 32;     // warp m offset (0..96)
    const int wn  = (wid >> 2) * 32;    // warp n offset (0 or 32)
    const int bm  = blockIdx.y * 128;
    const int bn  = blockIdx.x * 64;

    const int kp = K >> 5;
    const f16* pAh = Ah + (size_t)blockIdx.y * kp * APIECE;
    // B: 64-row sub-range of the 128-row tiled pieces
    const f16* pBh = Bh + (size_t)(blockIdx.x >> 1) * kp * APIECE
                        + (size_t)(blockIdx.x & 1) * 64 * GLD2;

    if (tid == 0) {
#pragma unroll
        for (int s = 0; s < GNST; s++) {
            MBAR_INIT(dbar + s * 8, 1);
            MBAR_INIT(fbar + s * 8, 8);
        }
    }
    __syncthreads();

    auto issue = [&](int s, int c) {
        const uint32_t mb = dbar + s * 8;
        const uint32_t d  = sb + s * STG2;
        MBAR_EXPECT(mb, STG2);
        bulkcp(d,         pAh + (size_t)c * APIECE, GAT_B, mb);
        bulkcp(d + GAT_B, pBh + (size_t)c * APIECE, GBT_B, mb);
    };

    if (tid == 0) { issue(0, 0); issue(1, 1); issue(2, 2); }

    const uint32_t aLane = (uint32_t)((lid & 15) * GLD2 + ((lid >> 4) << 3)) * 2;
    const uint32_t bLane = (uint32_t)((wn + lid) * GLD2) * 2;

    float acc[2][4][4];
#pragma unroll
    for (int mi = 0; mi < 2; mi++)
#pragma unroll
        for (int ni = 0; ni < 4; ni++)
#pragma unroll
            for (int r = 0; r < 4; r++) acc[mi][ni][r] = 0.f;

    int dph[GNST] = {0, 0, 0, 0}, fph[GNST] = {0, 0, 0, 0};
    for (int c = 0; c < kp; c++) {
        const int s = c & 3;
        MBAR_WAIT(dbar + s * 8, dph[s]); dph[s] ^= 1;

        const uint32_t sAH = sb + s * STG2;
        const uint32_t sBH = sAH + GAT_B;

#pragma unroll
        for (int k2 = 0; k2 < 2; k2++) {
            const uint32_t kOff = k2 * 32;
            uint32_t bh0[4], bh1[4];
            ldsm4(bh0, sBH + bLane + kOff);
            ldsm4(bh1, sBH + bLane + kOff + 16);
#pragma unroll
            for (int mi = 0; mi < 2; mi++) {
                const uint32_t rOff = (uint32_t)(wm + mi * 16) * 80 + aLane + kOff;
                uint32_t ah[4];
                ldsm4(ah, sAH + rOff);
#pragma unroll
                for (int ni = 0; ni < 4; ni++)
                    mmah(acc[mi][ni], ah[0], ah[1], ah[2], ah[3], bh0[ni], bh1[ni]);
            }
        }

        if (lid == 0) MBAR_ARRIVE(fbar + s * 8);
        if (tid == 0 && c + 3 < kp) {
            const int t = (c + 3) & 3;
            if (c + 3 >= GNST) { MBAR_WAIT(fbar + t * 8, fph[t]); fph[t] ^= 1; }
            issue(t, c + 3);
        }
    }

    if (kmode) {
        const int reg = bn >> 10;                // 0=Q, 1=K, 2=V
        f16* dbuf = (reg == 0) ? qh : ((reg == 1) ? kh : vh);
        const float scl = (reg == 0) ? SCALE : 1.f;
#pragma unroll
        for (int ni = 0; ni < 4; ni++) {
            const int col = bn + wn + ni * 8 + tg * 2;
            const float bx = bias[col], by = bias[col + 1];
            const int colq = col & 1023;
            const int hh = colq >> 6, dd = colq & 63;
#pragma unroll
            for (int mi = 0; mi < 2; mi++) {
                const int row = bm + wm + mi * 16 + g;
                uint32_t hi0 = packh((acc[mi][ni][0] + bx) * scl,
                                     (acc[mi][ni][1] + by) * scl);
                uint32_t hi1 = packh((acc[mi][ni][2] + bx) * scl,
                                     (acc[mi][ni][3] + by) * scl);
#pragma unroll
                for (int rr = 0; rr < 2; rr++) {
                    const int r2 = row + rr * 8;
                    const size_t dst =
                        (size_t)((((r2 >> 11) << 4) + hh) * 16 + ((r2 >> 7) & 15)) * KPIECE
                        + (size_t)(r2 & 127) * AQLD + dd;
                    *(uint32_t*)&dbuf[dst] = rr ? hi1 : hi0;
                }
            }
        }
    } else {
#pragma unroll
        for (int ni = 0; ni < 4; ni++) {
            const int col = bn + wn + ni * 8 + tg * 2;
            const float bx = bias[col], by = bias[col + 1];
#pragma unroll
            for (int mi = 0; mi < 2; mi++) {
                const int row = bm + wm + mi * 16 + g;
                float2 w0, w1;
                w0.x = acc[mi][ni][0] + bx;
                w0.y = acc[mi][ni][1] + by;
                w1.x = acc[mi][ni][2] + bx;
                w1.y = acc[mi][ni][3] + by;
                *(float2*)&C[(size_t)row * N + col]       = w0;
                *(float2*)&C[(size_t)(row + 8) * N + col] = w1;
            }
        }
    }
}

// ---------------------------------------------------------------------------
// fp16 flash attention (unchanged from round 16, passing)
// ---------------------------------------------------------------------------
#define QT_B (128 * AQLD * 2)
#define KT2_B (64 * AQLD * 2)
#define AST_B (2 * KT2_B)
#define ANST 4
#define OFF_K0 QT_B
#define ATT_MB (QT_B + ANST * AST_B)
#define ATT_SMEM (ATT_MB + 96)

__global__ __launch_bounds__(256, 2) void attn_tc(
    const f16* __restrict__ qh_g,
    const f16* __restrict__ kh_g, const f16* __restrict__ vh_g,
    f16* __restrict__ oh)
{
    extern __shared__ char smc[];
    const uint32_t sb = smem_u32(smc);
    const uint32_t dbar = sb + ATT_MB;
    const uint32_t fbar = dbar + 32;
    const uint32_t qbar = fbar + 32;

    const int tid = threadIdx.x;
    const int wid = tid >> 5;
    const int lid = tid & 31;
    const int g   = lid >> 2;
    const int tg  = lid & 3;
    const int qt  = blockIdx.x;
    const int bhx = blockIdx.y;
    const int b   = bhx >> 4;
    const int q0  = qt * 128;
    const size_t tok_base = (size_t)b * S_;
    const int hcol = (bhx & 15) * D_;
    const int wrow = wid * 16;

    if (tid == 0) {
#pragma unroll
        for (int s = 0; s < ANST; s++) {
            MBAR_INIT(dbar + s * 8, 1);
            MBAR_INIT(fbar + s * 8, 8);
        }
        MBAR_INIT(qbar, 1);
    }
    __syncthreads();

    const f16* pKh = kh_g + (size_t)bhx * 16 * KPIECE;
    const f16* pVh = vh_g + (size_t)bhx * 16 * KPIECE;

    auto issue_kv = [&](int s, int kt) {
        const uint32_t mb  = dbar + s * 8;
        const uint32_t dkb = sb + OFF_K0 + s * AST_B;
        MBAR_EXPECT(mb, AST_B);
        bulkcp(dkb,         pKh + (size_t)kt * KSUB, KT2_B, mb);
        bulkcp(dkb + KT2_B, pVh + (size_t)kt * KSUB, KT2_B, mb);
    };

    if (tid == 0) {
        MBAR_EXPECT(qbar, QT_B);
        bulkcp(sb, qh_g + ((size_t)bhx * 16 + qt) * KPIECE, QT_B, qbar);
        issue_kv(0, 0); issue_kv(1, 1); issue_kv(2, 2);
    }
    MBAR_WAIT(qbar, 0);

    const uint32_t qLane = (uint32_t)((wrow + (lid & 15)) * AQLD + ((lid >> 4) << 3)) * 2;
    const uint32_t rLane = (uint32_t)lid * 144;
    const uint32_t vLane = (uint32_t)(lid & 15) * 144 + ((lid >> 4) << 4);

    float acc_o[8][4];
#pragma unroll
    for (int dt = 0; dt < 8; dt++)
#pragma unroll
        for (int r = 0; r < 4; r++) acc_o[dt][r] = 0.f;
    float m0 = -INFINITY, m1 = -INFINITY, l0 = 0.f, l1 = 0.f;

    int dph[ANST] = {0, 0, 0, 0}, fph[ANST] = {0, 0, 0, 0};
    const int nkt = S_ / 64;
    for (int kt = 0; kt < nkt; kt++) {
        const int s = kt & 3;
        MBAR_WAIT(dbar + s * 8, dph[s]); dph[s] ^= 1;

        const uint32_t sKH = sb + OFF_K0 + s * AST_B;
        const uint32_t sVH = sKH + KT2_B;

        // ---- scores: q·k ----
        float accs[8][4];
#pragma unroll
        for (int nt = 0; nt < 8; nt++)
#pragma unroll
            for (int r = 0; r < 4; r++) accs[nt][r] = 0.f;

#pragma unroll
        for (int ks = 0; ks < 4; ks++) {
            const uint32_t kOff = ks * 32;
            uint32_t ah[4];
            ldsm4(ah, sb + qLane + kOff);
            uint32_t kh0[2][4], kh1[2][4];
#pragma unroll
            for (int n2 = 0; n2 < 2; n2++) {
                const uint32_t kAddr = n2 * (32 * 144) + rLane + kOff;
                ldsm4(kh0[n2], sKH + kAddr);
                ldsm4(kh1[n2], sKH + kAddr + 16);
            }
#pragma unroll
            for (int n2 = 0; n2 < 2; n2++)
#pragma unroll
                for (int q = 0; q < 4; q++)
                    mmah(accs[n2 * 4 + q], ah[0], ah[1], ah[2], ah[3],
                         kh0[n2][q], kh1[n2][q]);
        }

        // ---- online softmax ----
        float nm0 = m0, nm1 = m1;
#pragma unroll
        for (int nt = 0; nt < 8; nt++) {
            nm0 = fmaxf(nm0, fmaxf(accs[nt][0], accs[nt][1]));
            nm1 = fmaxf(nm1, fmaxf(accs[nt][2], accs[nt][3]));
        }
        nm0 = fmaxf(nm0, __shfl_xor_sync(0xffffffffu, nm0, 1));
        nm0 = fmaxf(nm0, __shfl_xor_sync(0xffffffffu, nm0, 2));
        nm1 = fmaxf(nm1, __shfl_xor_sync(0xffffffffu, nm1, 1));
        nm1 = fmaxf(nm1, __shfl_xor_sync(0xffffffffu, nm1, 2));
        const float corr0 = __expf(m0 - nm0);
        const float corr1 = __expf(m1 - nm1);
        float rs0 = 0.f, rs1 = 0.f;
#pragma unroll
        for (int nt = 0; nt < 8; nt++) {
            accs[nt][0] = __expf(accs[nt][0] - nm0);
            accs[nt][1] = __expf(accs[nt][1] - nm0);
            accs[nt][2] = __expf(accs[nt][2] - nm1);
            accs[nt][3] = __expf(accs[nt][3] - nm1);
            rs0 += accs[nt][0] + accs[nt][1];
            rs1 += accs[nt][2] + accs[nt][3];
        }
        rs0 += __shfl_xor_sync(0xffffffffu, rs0, 1);
        rs0 += __shfl_xor_sync(0xffffffffu, rs0, 2);
        rs1 += __shfl_xor_sync(0xffffffffu, rs1, 1);
        rs1 += __shfl_xor_sync(0xffffffffu, rs1, 2);
        l0 = l0 * corr0 + rs0;
        l1 = l1 * corr1 + rs1;
        m0 = nm0; m1 = nm1;
#pragma unroll
        for (int dt = 0; dt < 8; dt++) {
            acc_o[dt][0] *= corr0;
            acc_o[dt][1] *= corr0;
            acc_o[dt][2] *= corr1;
            acc_o[dt][3] *= corr1;
        }

        // ---- PV: p·v (V token-major via ldmatrix.trans) ----
#pragma unroll
        for (int kc = 0; kc < 4; kc++) {
            uint32_t pah[4];
            pah[0] = packh(accs[2 * kc][0],     accs[2 * kc][1]);
            pah[1] = packh(accs[2 * kc][2],     accs[2 * kc][3]);
            pah[2] = packh(accs[2 * kc + 1][0], accs[2 * kc + 1][1]);
            pah[3] = packh(accs[2 * kc + 1][2], accs[2 * kc + 1][3]);
            const uint32_t vBase = sVH + (uint32_t)(kc * 16) * 144 + vLane;
#pragma unroll
            for (int d2 = 0; d2 < 2; d2++) {
#pragma unroll
                for (int u = 0; u < 2; u++) {
                    uint32_t vr[4];
                    ldsm4t(vr, vBase + d2 * 64 + u * 32);
                    const int nt = d2 * 4 + u * 2;
                    mmah(acc_o[nt],     pah[0], pah[1], pah[2], pah[3], vr[0], vr[1]);
                    mmah(acc_o[nt + 1], pah[0], pah[1], pah[2], pah[3], vr[2], vr[3]);
                }
            }
        }

        if (lid == 0) MBAR_ARRIVE(fbar + s * 8);
        if (tid == 0 && kt + 3 < nkt) {
            const int t = (kt + 3) & 3;
            if (kt + 3 >= ANST) { MBAR_WAIT(fbar + t * 8, fph[t]); fph[t] ^= 1; }
            issue_kv(t, kt + 3);
        }
    }

    // ---- epilogue: write tiled fp16 output (A operand of o-proj) ----
    const float inv0 = 1.f / l0;
    const float inv1 = 1.f / l1;
    const int row0 = (int)(tok_base + q0 + wrow + g);
#pragma unroll
    for (int dt = 0; dt < 8; dt++) {
        const int col = hcol + dt * 8 + tg * 2;
        uint32_t hi0 = packh(acc_o[dt][0] * inv0, acc_o[dt][1] * inv0);
        uint32_t hi1 = packh(acc_o[dt][2] * inv1, acc_o[dt][3] * inv1);
#pragma unroll
        for (int rr = 0; rr < 2; rr++) {
            const int r2 = row0 + rr * 8;
            const size_t dst = ((size_t)((r2 >> 7) * 32 + (col >> 5))) * APIECE
                             + (size_t)(r2 & 127) * GLD2 + (col & 31);
            *(uint32_t*)&oh[dst] = rr ? hi1 : hi0;
        }
    }
}

// ---------------------------------------------------------------------------
extern "C" void kernel_launch(void* const* d_in, const int* in_sizes, int n_in,
                              void* d_out, int out_size)
{
    const float* x     = (const float*)d_in[0];
    const float* w_qkv = (const float*)d_in[1];
    const float* b_qkv = (const float*)d_in[2];
    const float* w_o   = (const float*)d_in[3];
    const float* b_o   = (const float*)d_in[4];
    float* out = (float*)d_out;

    f16 *p_xh, *p_wqh, *p_woh, *p_ath, *p_qh, *p_kh, *p_vh;
    cudaGetSymbolAddress((void**)&p_xh, g_xh);
    cudaGetSymbolAddress((void**)&p_wqh, g_wqh);
    cudaGetSymbolAddress((void**)&p_woh, g_woh);
    cudaGetSymbolAddress((void**)&p_ath, g_ath);
    cudaGetSymbolAddress((void**)&p_qh, g_qh);
    cudaGetSymbolAddress((void**)&p_kh, g_kh);
    cudaGetSymbolAddress((void**)&p_vh, g_vh);

    cudaFuncSetAttribute(gemm_f16, cudaFuncAttributeMaxDynamicSharedMemorySize,
                         GEMM_SMEM);
    cudaFuncSetAttribute(attn_tc, cudaFuncAttributeMaxDynamicSharedMemorySize,
                         ATT_SMEM);

    split_tiled<<<(M_TOK * HID) / 2048, 256>>>(x, p_xh, HID);
    split_tiled<<<(N_QKV * HID) / 2048, 256>>>(w_qkv, p_wqh, HID);
    split_tiled<<<(HID * QKV_) / 2048, 256>>>(w_o, p_woh, QKV_);

    // 1) QKV projection — emits Q (scaled), K, V directly as fp16 tiles
    {
        dim3 grid(N_QKV / 64, M_TOK / 128);
        gemm_f16<<<grid, 256, GEMM_SMEM>>>(p_xh, p_wqh, b_qkv, nullptr,
                                           p_qh, p_kh, p_vh,
                                           M_TOK, N_QKV, HID, 1);
    }
    // 2) attention (fully fp16 in/out)
    {
        dim3 grid(S_ / 128, B_ * H_);
        attn_tc<<<grid, 256, ATT_SMEM>>>(p_qh, p_kh, p_vh, p_ath);
    }
    // 3) output projection (fp32 out)
    {
        dim3 grid(QKV_ / 64, M_TOK / 128);
        gemm_f16<<<grid, 256, GEMM_SMEM>>>(p_ath, p_woh, b_o, out,
                                           nullptr, nullptr, nullptr,
                                           M_TOK, QKV_, HID, 0);
    }
}